// round 12
// baseline (speedup 1.0000x reference)
#include <cuda_runtime.h>
#include <cuda_bf16.h>
#include <math.h>

// ---------------------------------------------------------------------------
// CrossModalAttention, round 12: round OUTPUTS not inputs.
//  - Q and K projections: accurate 3-MMA split GEMMs (fused via grid.z),
//    output rounded once to bf16 (hi only) — no lo tensors downstream.
//  - attn: pass1 = QhKh bf16 + exp + rowsum + register-P PV;
//          pass2 = identical QhKh (1 MMA) + exp*inv -> attn (bitwise-same S).
//  - V/O projections: 1-MMA fast GEMM.
// ---------------------------------------------------------------------------

#define HIDDEN 1024
#define HEADS  16
#define DH     64
#define NBATCH 2
#define SEQ    2048
#define MROWS  (NBATCH * SEQ)   // 4096
#define LN_EPS 1e-5f

__device__ __nv_bfloat16 g_Wqh[HIDDEN * HIDDEN], g_Wql[HIDDEN * HIDDEN];
__device__ __nv_bfloat16 g_Wkh[HIDDEN * HIDDEN], g_Wkl[HIDDEN * HIDDEN];
__device__ __nv_bfloat16 g_Wvh[HIDDEN * HIDDEN], g_Woh[HIDDEN * HIDDEN];
__device__ __nv_bfloat16 g_Xqh[MROWS * HIDDEN], g_Xql[MROWS * HIDDEN];
__device__ __nv_bfloat16 g_Xkh[MROWS * HIDDEN], g_Xkl[MROWS * HIDDEN];
__device__ __nv_bfloat16 g_Xvh[MROWS * HIDDEN];
__device__ __nv_bfloat16 g_Qh[MROWS * HIDDEN];
__device__ __nv_bfloat16 g_Kh[MROWS * HIDDEN];
__device__ __nv_bfloat16 g_Vh[MROWS * HIDDEN];
__device__ __nv_bfloat16 g_ctx[MROWS * HIDDEN];
__device__ float g_proj[MROWS * HIDDEN];

// ---------------------------------------------------------------------------
// PTX helpers
// ---------------------------------------------------------------------------
__device__ __forceinline__ void mma_bf16(float* c, const unsigned* a, const unsigned* b) {
    asm volatile(
        "mma.sync.aligned.m16n8k16.row.col.f32.bf16.bf16.f32 "
        "{%0,%1,%2,%3}, {%4,%5,%6,%7}, {%8,%9}, {%0,%1,%2,%3};\n"
        : "+f"(c[0]), "+f"(c[1]), "+f"(c[2]), "+f"(c[3])
        : "r"(a[0]), "r"(a[1]), "r"(a[2]), "r"(a[3]), "r"(b[0]), "r"(b[1]));
}
__device__ __forceinline__ void ldsm_x4(unsigned* r, const __nv_bfloat16* p) {
    unsigned a = (unsigned)__cvta_generic_to_shared(p);
    asm volatile("ldmatrix.sync.aligned.m8n8.x4.shared.b16 {%0,%1,%2,%3}, [%4];\n"
                 : "=r"(r[0]), "=r"(r[1]), "=r"(r[2]), "=r"(r[3]) : "r"(a));
}
__device__ __forceinline__ void ldsm_x4t(unsigned* r, const __nv_bfloat16* p) {
    unsigned a = (unsigned)__cvta_generic_to_shared(p);
    asm volatile("ldmatrix.sync.aligned.m8n8.x4.trans.shared.b16 {%0,%1,%2,%3}, [%4];\n"
                 : "=r"(r[0]), "=r"(r[1]), "=r"(r[2]), "=r"(r[3]) : "r"(a));
}
#define CP_ASYNC16(dst, src) \
    asm volatile("cp.async.cg.shared.global [%0], [%1], 16;\n" :: "r"(dst), "l"(src))
#define CP_COMMIT() asm volatile("cp.async.commit_group;\n")
#define CP_WAIT(n)  asm volatile("cp.async.wait_group %0;\n" :: "n"(n))

__device__ __forceinline__ unsigned pack_bf2(float x, float y) {
    __nv_bfloat162 h = __float22bfloat162_rn(make_float2(x, y));
    return *(unsigned*)&h;
}
__device__ __forceinline__ void split_pair(float x, float y,
                                           __nv_bfloat162& hi, __nv_bfloat162& lo) {
    hi = __float22bfloat162_rn(make_float2(x, y));
    float2 hf = __bfloat1622float2(hi);
    lo = __float22bfloat162_rn(make_float2(x - hf.x, y - hf.y));
}

// ---------------------------------------------------------------------------
// presplit: z=0 Wq(split) 1 q(split) 2 Wk(split) 3 k(split) 4 Wv 5 Wo 6 v
// ---------------------------------------------------------------------------
#define W4 (HIDDEN * HIDDEN / 4)
#define X4 (MROWS * HIDDEN / 4)

__global__ void presplit_all(
    const float* __restrict__ Wq, const float* __restrict__ q,
    const float* __restrict__ Wk, const float* __restrict__ k,
    const float* __restrict__ Wv, const float* __restrict__ Wo,
    const float* __restrict__ v,
    __nv_bfloat16* __restrict__ Wqh, __nv_bfloat16* __restrict__ Wql,
    __nv_bfloat16* __restrict__ Xqh, __nv_bfloat16* __restrict__ Xql,
    __nv_bfloat16* __restrict__ Wkh, __nv_bfloat16* __restrict__ Wkl,
    __nv_bfloat16* __restrict__ Xkh, __nv_bfloat16* __restrict__ Xkl,
    __nv_bfloat16* __restrict__ Wvh, __nv_bfloat16* __restrict__ Woh,
    __nv_bfloat16* __restrict__ Xvh) {
    const int z = blockIdx.y;
    const int i = blockIdx.x * blockDim.x + threadIdx.x;
    const float* src; __nv_bfloat16 *h, *l = nullptr; int n4;
    switch (z) {
        case 0: src = Wq; h = Wqh; l = Wql; n4 = W4; break;
        case 1: src = q;  h = Xqh; l = Xql; n4 = X4; break;
        case 2: src = Wk; h = Wkh; l = Wkl; n4 = W4; break;
        case 3: src = k;  h = Xkh; l = Xkl; n4 = X4; break;
        case 4: src = Wv; h = Wvh; n4 = W4; break;
        case 5: src = Wo; h = Woh; n4 = W4; break;
        default: src = v; h = Xvh; n4 = X4; break;
    }
    if (i >= n4) return;
    float4 val = ((const float4*)src)[i];
    if (l) {
        __nv_bfloat162 h0, l0, h1, l1;
        split_pair(val.x, val.y, h0, l0);
        split_pair(val.z, val.w, h1, l1);
        ((__nv_bfloat162*)h)[2 * i]     = h0;
        ((__nv_bfloat162*)h)[2 * i + 1] = h1;
        ((__nv_bfloat162*)l)[2 * i]     = l0;
        ((__nv_bfloat162*)l)[2 * i + 1] = l1;
    } else {
        ((__nv_bfloat162*)h)[2 * i]     = __float22bfloat162_rn(make_float2(val.x, val.y));
        ((__nv_bfloat162*)h)[2 * i + 1] = __float22bfloat162_rn(make_float2(val.z, val.w));
    }
}

// ---------------------------------------------------------------------------
// staging: 128 rows x 32 bf16 (row stride 40), 256 threads
// ---------------------------------------------------------------------------
__device__ __forceinline__ void stage_tile(unsigned smbase, const __nv_bfloat16* g, int t) {
#pragma unroll
    for (int r = 0; r < 2; ++r) {
        int idx = t + r * 256;
        int row = idx >> 2;
        int c8  = (idx & 3) * 8;
        CP_ASYNC16(smbase + (unsigned)(row * 40 + c8) * 2, g + (size_t)row * HIDDEN + c8);
    }
}

__device__ __forceinline__ void load_bfrag(unsigned bf[4][2], const __nv_bfloat16* B,
                                           int wn, int ks, int lane) {
#pragma unroll
    for (int jj = 0; jj < 2; ++jj) {
        unsigned r[4];
        int br = wn * 32 + jj * 16 + (lane & 15);
        int bc = ks + ((lane & 16) ? 8 : 0);
        ldsm_x4(r, &B[br * 40 + bc]);
        bf[2 * jj][0] = r[0]; bf[2 * jj][1] = r[2];
        bf[2 * jj + 1][0] = r[1]; bf[2 * jj + 1][1] = r[3];
    }
}

// ---------------------------------------------------------------------------
// gemm_split (Q and K fused via grid.z): 3-MMA accurate, OUTPUT = bf16 hi only
// ---------------------------------------------------------------------------
#define GS_STAGE 10240
#define GS_SMEM  (8 * GS_STAGE)

__global__ __launch_bounds__(256, 2) void gemm_split_kernel(
    const __nv_bfloat16* __restrict__ A0g, const __nv_bfloat16* __restrict__ A1g,
    const __nv_bfloat16* __restrict__ L0g, const __nv_bfloat16* __restrict__ L1g,
    const __nv_bfloat16* __restrict__ W0g, const __nv_bfloat16* __restrict__ W1g,
    const __nv_bfloat16* __restrict__ V0g, const __nv_bfloat16* __restrict__ V1g,
    const float* __restrict__ b0g, const float* __restrict__ b1g,
    __nv_bfloat16* __restrict__ O0g, __nv_bfloat16* __restrict__ O1g) {
    extern __shared__ __align__(16) char sm[];
    const unsigned sb = (unsigned)__cvta_generic_to_shared(sm);

    const int z = blockIdx.z;
    const __nv_bfloat16* Ahg = z ? A1g : A0g;
    const __nv_bfloat16* Alg = z ? L1g : L0g;
    const __nv_bfloat16* Whg = z ? W1g : W0g;
    const __nv_bfloat16* Wlg = z ? V1g : V0g;
    const float* bias = z ? b1g : b0g;
    __nv_bfloat16* OH = z ? O1g : O0g;

    const int t = threadIdx.x, lane = t & 31, warp = t >> 5;
    const int wm = warp >> 2, wn = warp & 3;
    const int m0 = blockIdx.y * 128, n0 = blockIdx.x * 128;

    const __nv_bfloat16* Ah0 = Ahg + (size_t)m0 * HIDDEN;
    const __nv_bfloat16* Al0 = Alg + (size_t)m0 * HIDDEN;
    const __nv_bfloat16* Wh0 = Whg + (size_t)n0 * HIDDEN;
    const __nv_bfloat16* Wl0 = Wlg + (size_t)n0 * HIDDEN;

    float acc[4][4][4] = {};

    stage_tile(sb + 0 * GS_STAGE, Ah0, t);
    stage_tile(sb + 1 * GS_STAGE, Al0, t);
    stage_tile(sb + 2 * GS_STAGE, Wh0, t);
    stage_tile(sb + 3 * GS_STAGE, Wl0, t);
    CP_COMMIT();

    for (int i = 0; i < 32; ++i) {
        if (i < 31) {
            int k1 = (i + 1) * 32;
            unsigned s1 = sb + ((i + 1) & 1) * 4 * GS_STAGE;
            stage_tile(s1 + 0 * GS_STAGE, Ah0 + k1, t);
            stage_tile(s1 + 1 * GS_STAGE, Al0 + k1, t);
            stage_tile(s1 + 2 * GS_STAGE, Wh0 + k1, t);
            stage_tile(s1 + 3 * GS_STAGE, Wl0 + k1, t);
            CP_COMMIT();
            CP_WAIT(1);
        } else {
            CP_WAIT(0);
        }
        __syncthreads();

        char* base = sm + (i & 1) * 4 * GS_STAGE;
        const __nv_bfloat16* Ah = (const __nv_bfloat16*)(base);
        const __nv_bfloat16* Al = (const __nv_bfloat16*)(base + GS_STAGE);
        const __nv_bfloat16* Bh = (const __nv_bfloat16*)(base + 2 * GS_STAGE);
        const __nv_bfloat16* Bl = (const __nv_bfloat16*)(base + 3 * GS_STAGE);

#pragma unroll
        for (int ks = 0; ks < 32; ks += 16) {
            unsigned ah[4][4], al[4][4], bhf[4][2], blf[4][2];
            load_bfrag(bhf, Bh, wn, ks, lane);
            load_bfrag(blf, Bl, wn, ks, lane);
#pragma unroll
            for (int ii = 0; ii < 4; ++ii) {
                int ar = wm * 64 + ii * 16 + (lane & 15);
                int ac = ks + ((lane & 16) ? 8 : 0);
                ldsm_x4(ah[ii], &Ah[ar * 40 + ac]);
                ldsm_x4(al[ii], &Al[ar * 40 + ac]);
            }
#pragma unroll
            for (int ii = 0; ii < 4; ++ii)
#pragma unroll
                for (int j = 0; j < 4; ++j) {
                    mma_bf16(acc[ii][j], ah[ii], bhf[j]);
                    mma_bf16(acc[ii][j], ah[ii], blf[j]);
                    mma_bf16(acc[ii][j], al[ii], bhf[j]);
                }
        }
        __syncthreads();
    }

    const int g = lane >> 2, t2 = (lane & 3) * 2;
#pragma unroll
    for (int i = 0; i < 4; ++i) {
        int row = m0 + wm * 64 + i * 16 + g;
#pragma unroll
        for (int j = 0; j < 4; ++j) {
            int col = n0 + wn * 32 + j * 8 + t2;
            float bb0 = bias[col], bb1 = bias[col + 1];
            *(__nv_bfloat162*)&OH[(size_t)row * HIDDEN + col] =
                __float22bfloat162_rn(make_float2(acc[i][j][0] + bb0, acc[i][j][1] + bb1));
            *(__nv_bfloat162*)&OH[(size_t)(row + 8) * HIDDEN + col] =
                __float22bfloat162_rn(make_float2(acc[i][j][2] + bb0, acc[i][j][3] + bb1));
        }
    }
}

// ---------------------------------------------------------------------------
// gemm_fast: 1-MMA; grid.z selects pair; fp32 out if Of set.
// ---------------------------------------------------------------------------
__global__ __launch_bounds__(256, 2) void gemm_fast_kernel(
    const __nv_bfloat16* __restrict__ A0g, const __nv_bfloat16* __restrict__ A1g,
    const __nv_bfloat16* __restrict__ W0g, const __nv_bfloat16* __restrict__ W1g,
    const float* __restrict__ b0g, const float* __restrict__ b1g,
    __nv_bfloat16* __restrict__ O0g, __nv_bfloat16* __restrict__ O1g,
    float* __restrict__ Of) {
    __shared__ __align__(16) __nv_bfloat16 smf[2][2][128 * 40];
    const int t = threadIdx.x, lane = t & 31, warp = t >> 5;
    const int wm = warp >> 2, wn = warp & 3;
    const int m0 = blockIdx.y * 128, n0 = blockIdx.x * 128;
    const int z = blockIdx.z;

    const __nv_bfloat16* A0 = (z ? A1g : A0g) + (size_t)m0 * HIDDEN;
    const __nv_bfloat16* W0 = (z ? W1g : W0g) + (size_t)n0 * HIDDEN;
    const float* bias = z ? b1g : b0g;
    __nv_bfloat16* Obf = z ? O1g : O0g;

    float acc[4][4][4] = {};

    stage_tile((unsigned)__cvta_generic_to_shared(smf[0][0]), A0, t);
    stage_tile((unsigned)__cvta_generic_to_shared(smf[0][1]), W0, t);
    CP_COMMIT();

    for (int i = 0; i < 32; ++i) {
        if (i < 31) {
            int k1 = (i + 1) * 32;
            int s = (i + 1) & 1;
            stage_tile((unsigned)__cvta_generic_to_shared(smf[s][0]), A0 + k1, t);
            stage_tile((unsigned)__cvta_generic_to_shared(smf[s][1]), W0 + k1, t);
            CP_COMMIT();
            CP_WAIT(1);
        } else {
            CP_WAIT(0);
        }
        __syncthreads();

        const __nv_bfloat16* Ah = smf[i & 1][0];
        const __nv_bfloat16* Bh = smf[i & 1][1];

#pragma unroll
        for (int ks = 0; ks < 32; ks += 16) {
            unsigned ah[4][4], bhf[4][2];
            load_bfrag(bhf, Bh, wn, ks, lane);
#pragma unroll
            for (int ii = 0; ii < 4; ++ii) {
                int ar = wm * 64 + ii * 16 + (lane & 15);
                int ac = ks + ((lane & 16) ? 8 : 0);
                ldsm_x4(ah[ii], &Ah[ar * 40 + ac]);
            }
#pragma unroll
            for (int ii = 0; ii < 4; ++ii)
#pragma unroll
                for (int j = 0; j < 4; ++j)
                    mma_bf16(acc[ii][j], ah[ii], bhf[j]);
        }
        __syncthreads();
    }

    const int g = lane >> 2, t2 = (lane & 3) * 2;
    if (Of) {
#pragma unroll
        for (int i = 0; i < 4; ++i) {
            int row = m0 + wm * 64 + i * 16 + g;
#pragma unroll
            for (int j = 0; j < 4; ++j) {
                int col = n0 + wn * 32 + j * 8 + t2;
                float bb0 = bias[col], bb1 = bias[col + 1];
                *(float2*)&Of[(size_t)row * HIDDEN + col] =
                    make_float2(acc[i][j][0] + bb0, acc[i][j][1] + bb1);
                *(float2*)&Of[(size_t)(row + 8) * HIDDEN + col] =
                    make_float2(acc[i][j][2] + bb0, acc[i][j][3] + bb1);
            }
        }
    } else {
#pragma unroll
        for (int i = 0; i < 4; ++i) {
            int row = m0 + wm * 64 + i * 16 + g;
#pragma unroll
            for (int j = 0; j < 4; ++j) {
                int col = n0 + wn * 32 + j * 8 + t2;
                float bb0 = bias[col], bb1 = bias[col + 1];
                *(__nv_bfloat162*)&Obf[(size_t)row * HIDDEN + col] =
                    __float22bfloat162_rn(make_float2(acc[i][j][0] + bb0, acc[i][j][1] + bb1));
                *(__nv_bfloat162*)&Obf[(size_t)(row + 8) * HIDDEN + col] =
                    __float22bfloat162_rn(make_float2(acc[i][j][2] + bb0, acc[i][j][3] + bb1));
            }
        }
    }
}

// ---------------------------------------------------------------------------
// Fused attention: q-tile 64, 256 threads, 8 warps (wm 4 x wn 2), 2 CTAs/SM.
// S = Qh·Kh bf16 in BOTH passes (bitwise identical); no Q-lo anywhere.
// smem: QH 0(9216), K 9216(2x18432 -> ends 46080),
//       V 46080(2x18432 -> ends 82944; reused as red 64x66 f32 = 16896),
//       PART 82944(512), INV 83456(256) -> 83712
// ---------------------------------------------------------------------------
#define A_QH 0
#define A_K  9216
#define A_V  46080
#define A_PART 82944
#define A_INV  83456
#define A_SMEM 83712

__device__ __forceinline__ void stage_q64(unsigned sm, const __nv_bfloat16* g, int t) {
#pragma unroll
    for (int r = 0; r < 2; ++r) {
        int idx = t + r * 256;
        int row = idx >> 3;
        int c8  = (idx & 7) * 8;
        CP_ASYNC16(sm + (unsigned)(row * 72 + c8) * 2, g + (size_t)row * HIDDEN + c8);
    }
}
__device__ __forceinline__ void stage_k128(unsigned sm, const __nv_bfloat16* g, int t) {
#pragma unroll
    for (int r = 0; r < 4; ++r) {
        int idx = t + r * 256;
        int row = idx >> 3;
        int c8  = (idx & 7) * 8;
        CP_ASYNC16(sm + (unsigned)(row * 72 + c8) * 2, g + (size_t)row * HIDDEN + c8);
    }
}

__global__ __launch_bounds__(256, 2) void attn_fused_kernel(
    const __nv_bfloat16* __restrict__ Qh,
    const __nv_bfloat16* __restrict__ Kh,
    const __nv_bfloat16* __restrict__ Vh,
    const float* __restrict__ temp,
    float* __restrict__ attn, __nv_bfloat16* __restrict__ ctx) {
    extern __shared__ __align__(16) char smraw[];
    __nv_bfloat16* q_h = (__nv_bfloat16*)(smraw + A_QH);
    float* red    = (float*)(smraw + A_V);
    float* part   = (float*)(smraw + A_PART);
    float* sm_inv = (float*)(smraw + A_INV);
    const unsigned sb = (unsigned)__cvta_generic_to_shared(smraw);

    const int t = threadIdx.x, lane = t & 31, wid = t >> 5;
    const int wm = wid >> 1, wn = wid & 1;
    const int bh = blockIdx.y, b = bh >> 4, h = bh & 15;
    const int q0 = blockIdx.x * 64;
    const float ts = temp[0];
    const int g = lane >> 2, t2 = (lane & 3) * 2;
    const int lr = lane & 15, hc = (lane & 16) ? 8 : 0;

    const size_t qoff = (size_t)(b * SEQ + q0) * HIDDEN + h * DH;
    const size_t koff = (size_t)(b * SEQ) * HIDDEN + h * DH;

    // prologue: Q (group 0), K0 + V0 (group 1)
    stage_q64(sb + A_QH, Qh + qoff, t);
    CP_COMMIT();
    stage_k128(sb + A_K, Kh + koff, t);
    stage_k128(sb + A_V, Vh + koff, t);
    CP_COMMIT();

    CP_WAIT(1);
    __syncthreads();
    unsigned aqh_f[4][4];
#pragma unroll
    for (int kd = 0; kd < 4; ++kd)
        ldsm_x4(aqh_f[kd], &q_h[(wm * 16 + lr) * 72 + kd * 16 + hc]);

    // ---------------- PASS 1: QK bf16 + exp + rowsum + PV (register P) ------
    float acc[8][4] = {};
    float rs0 = 0.f, rs1 = 0.f;

    for (int kt = 0; kt < 16; ++kt) {
        __syncthreads();
        if (kt < 15) {
            size_t go = (size_t)(kt + 1) * 128 * HIDDEN;
            stage_k128(sb + A_K + ((kt + 1) & 1) * 18432, Kh + koff + go, t);
            stage_k128(sb + A_V + ((kt + 1) & 1) * 18432, Vh + koff + go, t);
            CP_COMMIT();
            CP_WAIT(1);
        } else {
            CP_WAIT(0);
        }
        __syncthreads();

        const __nv_bfloat16* k_h = (const __nv_bfloat16*)(smraw + A_K + (kt & 1) * 18432);
        const __nv_bfloat16* v_h = (const __nv_bfloat16*)(smraw + A_V + (kt & 1) * 18432);

        float c[8][4] = {};
#pragma unroll
        for (int kd = 0; kd < 4; ++kd) {
#pragma unroll
            for (int jp = 0; jp < 4; ++jp) {
                unsigned bb[4];
                ldsm_x4(bb, &k_h[(wn * 64 + jp * 16 + lr) * 72 + kd * 16 + hc]);
                unsigned be[2] = {bb[0], bb[2]}, bo[2] = {bb[1], bb[3]};
                mma_bf16(c[2 * jp],     aqh_f[kd], be);
                mma_bf16(c[2 * jp + 1], aqh_f[kd], bo);
            }
        }

#pragma unroll
        for (int j = 0; j < 8; ++j) {
            c[j][0] = __expf(c[j][0] * ts);
            c[j][1] = __expf(c[j][1] * ts);
            c[j][2] = __expf(c[j][2] * ts);
            c[j][3] = __expf(c[j][3] * ts);
            rs0 += c[j][0] + c[j][1];
            rs1 += c[j][2] + c[j][3];
        }

#pragma unroll
        for (int j2 = 0; j2 < 4; ++j2) {
            unsigned ap[4];
            ap[0] = pack_bf2(c[2 * j2][0],     c[2 * j2][1]);
            ap[1] = pack_bf2(c[2 * j2][2],     c[2 * j2][3]);
            ap[2] = pack_bf2(c[2 * j2 + 1][0], c[2 * j2 + 1][1]);
            ap[3] = pack_bf2(c[2 * j2 + 1][2], c[2 * j2 + 1][3]);
#pragma unroll
            for (int djp = 0; djp < 4; ++djp) {
                unsigned bv[4];
                ldsm_x4t(bv, &v_h[(wn * 64 + j2 * 16 + lr) * 72 + djp * 16 + hc]);
                unsigned b0[2] = {bv[0], bv[1]}, b1[2] = {bv[2], bv[3]};
                mma_bf16(acc[2 * djp],     ap, b0);
                mma_bf16(acc[2 * djp + 1], ap, b1);
            }
        }
    }

    // rowsum reduce -> part[wn][64]
    rs0 += __shfl_xor_sync(0xffffffffu, rs0, 1);
    rs0 += __shfl_xor_sync(0xffffffffu, rs0, 2);
    rs1 += __shfl_xor_sync(0xffffffffu, rs1, 1);
    rs1 += __shfl_xor_sync(0xffffffffu, rs1, 2);
    if ((lane & 3) == 0) {
        part[wn * 64 + wm * 16 + g]     = rs0;
        part[wn * 64 + wm * 16 + g + 8] = rs1;
    }
    __syncthreads();

    // prefetch pass2 K0 into buffer 0
    stage_k128(sb + A_K, Kh + koff, t);
    CP_COMMIT();

    if (t < 64)
        sm_inv[t] = 1.0f / (part[t] + part[64 + t]);

    // ctx reduction across wn (deterministic 2-step) into red[64][66]
    if (wn == 0) {
#pragma unroll
        for (int dj = 0; dj < 8; ++dj) {
            int r0 = wm * 16 + g, d = dj * 8 + t2;
            red[r0 * 66 + d]           = acc[dj][0];
            red[r0 * 66 + d + 1]       = acc[dj][1];
            red[(r0 + 8) * 66 + d]     = acc[dj][2];
            red[(r0 + 8) * 66 + d + 1] = acc[dj][3];
        }
    }
    __syncthreads();
    if (wn == 1) {
#pragma unroll
        for (int dj = 0; dj < 8; ++dj) {
            int r0 = wm * 16 + g, d = dj * 8 + t2;
            red[r0 * 66 + d]           += acc[dj][0];
            red[r0 * 66 + d + 1]       += acc[dj][1];
            red[(r0 + 8) * 66 + d]     += acc[dj][2];
            red[(r0 + 8) * 66 + d + 1] += acc[dj][3];
        }
    }
    __syncthreads();

    // ctx = red * inv (bf16)
    {
        int row = t >> 2, d0 = (t & 3) * 16;
        float iv = sm_inv[row];
        size_t o = (size_t)(b * SEQ + q0 + row) * HIDDEN + h * DH + d0;
#pragma unroll
        for (int u = 0; u < 8; ++u) {
            float x = red[row * 66 + d0 + 2 * u]     * iv;
            float y = red[row * 66 + d0 + 2 * u + 1] * iv;
            *(__nv_bfloat162*)&ctx[o + 2 * u] =
                __float22bfloat162_rn(make_float2(x, y));
        }
    }

    // ---------------- PASS 2: identical S = Qh·Kh -> attn write -------------
    for (int kt = 0; kt < 16; ++kt) {
        __syncthreads();
        if (kt < 15) {
            size_t go = (size_t)(kt + 1) * 128 * HIDDEN;
            stage_k128(sb + A_K + ((kt + 1) & 1) * 18432, Kh + koff + go, t);
            CP_COMMIT();
            CP_WAIT(1);
        } else {
            CP_WAIT(0);
        }
        __syncthreads();

        const __nv_bfloat16* k_h = (const __nv_bfloat16*)(smraw + A_K + (kt & 1) * 18432);

        float c[8][4] = {};
#pragma unroll
        for (int kd = 0; kd < 4; ++kd) {
#pragma unroll
            for (int jp = 0; jp < 4; ++jp) {
                unsigned bb[4];
                ldsm_x4(bb, &k_h[(wn * 64 + jp * 16 + lr) * 72 + kd * 16 + hc]);
                unsigned be[2] = {bb[0], bb[2]}, bo[2] = {bb[1], bb[3]};
                mma_bf16(c[2 * jp],     aqh_f[kd], be);
                mma_bf16(c[2 * jp + 1], aqh_f[kd], bo);
            }
        }

        int rl = wm * 16 + g;
        float iv0 = sm_inv[rl], iv1 = sm_inv[rl + 8];
        size_t r0 = ((size_t)bh * SEQ + q0 + rl) * SEQ + (size_t)kt * 128 + wn * 64;
        size_t r1 = r0 + (size_t)8 * SEQ;
#pragma unroll
        for (int j = 0; j < 8; ++j) {
            float p0 = __expf(c[j][0] * ts) * iv0;
            float p1 = __expf(c[j][1] * ts) * iv0;
            float p2 = __expf(c[j][2] * ts) * iv1;
            float p3 = __expf(c[j][3] * ts) * iv1;
            int col = j * 8 + t2;
            *(float2*)&attn[r0 + col] = make_float2(p0, p1);
            *(float2*)&attn[r1 + col] = make_float2(p2, p3);
        }
    }
}

// ---------------------------------------------------------------------------
// LayerNorm(proj + query) -> out
// ---------------------------------------------------------------------------
__global__ void ln_kernel(const float* __restrict__ proj,
                          const float* __restrict__ query,
                          const float* __restrict__ gamma,
                          const float* __restrict__ beta,
                          float* __restrict__ out) {
    __shared__ float red[8];
    const size_t row = blockIdx.x;
    const int t = threadIdx.x;

    float x[4];
    float s = 0.f;
#pragma unroll
    for (int i = 0; i < 4; ++i) {
        int c = t + i * 256;
        x[i] = proj[row * HIDDEN + c] + query[row * HIDDEN + c];
        s += x[i];
    }
#pragma unroll
    for (int o = 16; o; o >>= 1) s += __shfl_xor_sync(0xffffffffu, s, o);
    if ((t & 31) == 0) red[t >> 5] = s;
    __syncthreads();
    s = red[0];
#pragma unroll
    for (int i = 1; i < 8; ++i) s += red[i];
    const float mu = s * (1.f / HIDDEN);

    float vs = 0.f;
#pragma unroll
    for (int i = 0; i < 4; ++i) { float d = x[i] - mu; vs += d * d; }
#pragma unroll
    for (int o = 16; o; o >>= 1) vs += __shfl_xor_sync(0xffffffffu, vs, o);
    __syncthreads();
    if ((t & 31) == 0) red[t >> 5] = vs;
    __syncthreads();
    vs = red[0];
#pragma unroll
    for (int i = 1; i < 8; ++i) vs += red[i];
    const float inv = rsqrtf(vs * (1.f / HIDDEN) + LN_EPS);

#pragma unroll
    for (int i = 0; i < 4; ++i) {
        int c = t + i * 256;
        out[row * HIDDEN + c] = (x[i] - mu) * inv * gamma[c] + beta[c];
    }
}

// ---------------------------------------------------------------------------
// Launch
// ---------------------------------------------------------------------------
extern "C" void kernel_launch(void* const* d_in, const int* in_sizes, int n_in,
                              void* d_out, int out_size) {
    const float* query = (const float*)d_in[0];
    const float* key   = (const float*)d_in[1];
    const float* value = (const float*)d_in[2];
    const float* Wq    = (const float*)d_in[3];
    const float* bq    = (const float*)d_in[4];
    const float* Wk    = (const float*)d_in[5];
    const float* bk    = (const float*)d_in[6];
    const float* Wv    = (const float*)d_in[7];
    const float* bv    = (const float*)d_in[8];
    const float* Wo    = (const float*)d_in[9];
    const float* bo    = (const float*)d_in[10];
    const float* gamma = (const float*)d_in[11];
    const float* beta  = (const float*)d_in[12];
    const float* temp  = (const float*)d_in[13];

    float* out  = (float*)d_out;
    float* attn = out + (size_t)MROWS * HIDDEN;

    __nv_bfloat16 *Wqh, *Wql, *Wkh, *Wkl, *Wvh, *Woh;
    __nv_bfloat16 *Xqh, *Xql, *Xkh, *Xkl, *Xvh;
    __nv_bfloat16 *Qhp, *Khp, *Vhp, *ctxp;
    float *projp;
    cudaGetSymbolAddress((void**)&Wqh, g_Wqh); cudaGetSymbolAddress((void**)&Wql, g_Wql);
    cudaGetSymbolAddress((void**)&Wkh, g_Wkh); cudaGetSymbolAddress((void**)&Wkl, g_Wkl);
    cudaGetSymbolAddress((void**)&Wvh, g_Wvh); cudaGetSymbolAddress((void**)&Woh, g_Woh);
    cudaGetSymbolAddress((void**)&Xqh, g_Xqh); cudaGetSymbolAddress((void**)&Xql, g_Xql);
    cudaGetSymbolAddress((void**)&Xkh, g_Xkh); cudaGetSymbolAddress((void**)&Xkl, g_Xkl);
    cudaGetSymbolAddress((void**)&Xvh, g_Xvh);
    cudaGetSymbolAddress((void**)&Qhp, g_Qh);
    cudaGetSymbolAddress((void**)&Khp, g_Kh);
    cudaGetSymbolAddress((void**)&Vhp, g_Vh);
    cudaGetSymbolAddress((void**)&ctxp, g_ctx);
    cudaGetSymbolAddress((void**)&projp, g_proj);

    cudaFuncSetAttribute(gemm_split_kernel,
                         cudaFuncAttributeMaxDynamicSharedMemorySize, GS_SMEM);
    cudaFuncSetAttribute(attn_fused_kernel,
                         cudaFuncAttributeMaxDynamicSharedMemorySize, A_SMEM);

    // fused pre-split
    dim3 ps_grid(X4 / 256, 7);
    presplit_all<<<ps_grid, 256>>>(Wq, query, Wk, key, Wv, Wo, value,
                                   Wqh, Wql, Xqh, Xql, Wkh, Wkl, Xkh, Xkl,
                                   Wvh, Woh, Xvh);

    // Q + K projections (accurate split, fused via grid.z, hi-only out)
    dim3 qk_grid(HIDDEN / 128, MROWS / 128, 2);
    gemm_split_kernel<<<qk_grid, 256, GS_SMEM>>>(
        Xqh, Xkh, Xql, Xkl, Wqh, Wkh, Wql, Wkl, bq, bk, Qhp, Khp);

    // V projection
    dim3 pgrid(HIDDEN / 128, MROWS / 128);
    gemm_fast_kernel<<<pgrid, 256>>>(Xvh, Xvh, Wvh, Wvh, bv, bv,
                                     Vhp, Vhp, nullptr);

    // fused attention (q-tile 64, 2 CTAs/SM)
    dim3 at_grid(SEQ / 64, NBATCH * HEADS);   // (32, 32)
    attn_fused_kernel<<<at_grid, 256, A_SMEM>>>(Qhp, Khp, Vhp, temp, attn, ctxp);

    // output projection + LN
    gemm_fast_kernel<<<pgrid, 256>>>(ctxp, ctxp, Woh, Woh, bo, bo,
                                     nullptr, nullptr, projp);
    ln_kernel<<<MROWS, 256>>>(projp, query, gamma, beta, out);
}

// round 13
// speedup vs baseline: 1.1683x; 1.1683x over previous
#include <cuda_runtime.h>
#include <cuda_bf16.h>
#include <math.h>

// ---------------------------------------------------------------------------
// CrossModalAttention, round 13:
//  - Q/K projections: single-pass TF32 mma (m16n8k8) straight from fp32
//    inputs (truncation rounding), bf16 output. No presplit for Q/K path.
//  - presplit: only Wv, Wo, v -> bf16.
//  - attn: round-12 structure (QhKh both passes), ex2 + fused log2(inv).
// ---------------------------------------------------------------------------

#define HIDDEN 1024
#define HEADS  16
#define DH     64
#define NBATCH 2
#define SEQ    2048
#define MROWS  (NBATCH * SEQ)   // 4096
#define LN_EPS 1e-5f
#define LOG2E  1.44269504088896f

__device__ __nv_bfloat16 g_Wvh[HIDDEN * HIDDEN], g_Woh[HIDDEN * HIDDEN];
__device__ __nv_bfloat16 g_Xvh[MROWS * HIDDEN];
__device__ __nv_bfloat16 g_Qh[MROWS * HIDDEN];
__device__ __nv_bfloat16 g_Kh[MROWS * HIDDEN];
__device__ __nv_bfloat16 g_Vh[MROWS * HIDDEN];
__device__ __nv_bfloat16 g_ctx[MROWS * HIDDEN];
__device__ float g_proj[MROWS * HIDDEN];

// ---------------------------------------------------------------------------
// PTX helpers
// ---------------------------------------------------------------------------
__device__ __forceinline__ void mma_bf16(float* c, const unsigned* a, const unsigned* b) {
    asm volatile(
        "mma.sync.aligned.m16n8k16.row.col.f32.bf16.bf16.f32 "
        "{%0,%1,%2,%3}, {%4,%5,%6,%7}, {%8,%9}, {%0,%1,%2,%3};\n"
        : "+f"(c[0]), "+f"(c[1]), "+f"(c[2]), "+f"(c[3])
        : "r"(a[0]), "r"(a[1]), "r"(a[2]), "r"(a[3]), "r"(b[0]), "r"(b[1]));
}
__device__ __forceinline__ void mma_tf32(float* c, const float* a, const float* b) {
    asm volatile(
        "mma.sync.aligned.m16n8k8.row.col.f32.tf32.tf32.f32 "
        "{%0,%1,%2,%3}, {%4,%5,%6,%7}, {%8,%9}, {%0,%1,%2,%3};\n"
        : "+f"(c[0]), "+f"(c[1]), "+f"(c[2]), "+f"(c[3])
        : "r"(__float_as_uint(a[0])), "r"(__float_as_uint(a[1])),
          "r"(__float_as_uint(a[2])), "r"(__float_as_uint(a[3])),
          "r"(__float_as_uint(b[0])), "r"(__float_as_uint(b[1])));
}
__device__ __forceinline__ void ldsm_x4(unsigned* r, const __nv_bfloat16* p) {
    unsigned a = (unsigned)__cvta_generic_to_shared(p);
    asm volatile("ldmatrix.sync.aligned.m8n8.x4.shared.b16 {%0,%1,%2,%3}, [%4];\n"
                 : "=r"(r[0]), "=r"(r[1]), "=r"(r[2]), "=r"(r[3]) : "r"(a));
}
__device__ __forceinline__ void ldsm_x4t(unsigned* r, const __nv_bfloat16* p) {
    unsigned a = (unsigned)__cvta_generic_to_shared(p);
    asm volatile("ldmatrix.sync.aligned.m8n8.x4.trans.shared.b16 {%0,%1,%2,%3}, [%4];\n"
                 : "=r"(r[0]), "=r"(r[1]), "=r"(r[2]), "=r"(r[3]) : "r"(a));
}
#define CP_ASYNC16(dst, src) \
    asm volatile("cp.async.cg.shared.global [%0], [%1], 16;\n" :: "r"(dst), "l"(src))
#define CP_COMMIT() asm volatile("cp.async.commit_group;\n")
#define CP_WAIT(n)  asm volatile("cp.async.wait_group %0;\n" :: "n"(n))

__device__ __forceinline__ unsigned pack_bf2(float x, float y) {
    __nv_bfloat162 h = __float22bfloat162_rn(make_float2(x, y));
    return *(unsigned*)&h;
}
__device__ __forceinline__ float ex2f_fast(float x) {
    float y;
    asm("ex2.approx.f32 %0, %1;" : "=f"(y) : "f"(x));
    return y;
}
__device__ __forceinline__ float lg2f_fast(float x) {
    float y;
    asm("lg2.approx.f32 %0, %1;" : "=f"(y) : "f"(x));
    return y;
}

// ---------------------------------------------------------------------------
// presplit: z=0 Wv, 1 Wo, 2 v  -> bf16
// ---------------------------------------------------------------------------
#define W4 (HIDDEN * HIDDEN / 4)
#define X4 (MROWS * HIDDEN / 4)

__global__ void presplit3(const float* __restrict__ Wv, const float* __restrict__ Wo,
                          const float* __restrict__ v,
                          __nv_bfloat16* __restrict__ Wvh,
                          __nv_bfloat16* __restrict__ Woh,
                          __nv_bfloat16* __restrict__ Xvh) {
    const int z = blockIdx.y;
    const int i = blockIdx.x * blockDim.x + threadIdx.x;
    const float* src; __nv_bfloat16* h; int n4;
    switch (z) {
        case 0: src = Wv; h = Wvh; n4 = W4; break;
        case 1: src = Wo; h = Woh; n4 = W4; break;
        default: src = v; h = Xvh; n4 = X4; break;
    }
    if (i >= n4) return;
    float4 val = ((const float4*)src)[i];
    ((__nv_bfloat162*)h)[2 * i]     = __float22bfloat162_rn(make_float2(val.x, val.y));
    ((__nv_bfloat162*)h)[2 * i + 1] = __float22bfloat162_rn(make_float2(val.z, val.w));
}

// ---------------------------------------------------------------------------
// TF32 GEMM (Q and K projections, grid.z selects):
//   C[4096,1024] = A[4096,1024] @ W[1024,1024]^T + bias  -> bf16
// Block 128x128, BK=32, 8 warps (wm2 x wn4), warp tile 64x32.
// smem: fp32 tiles, row stride 36 floats; 2 stages x (A 18432B + W 18432B).
// ---------------------------------------------------------------------------
#define TF_TILE 18432
#define TF_SMEM (4 * TF_TILE)    // 73728

__device__ __forceinline__ void stage_f32(unsigned smbase, const float* g, int t) {
#pragma unroll
    for (int r = 0; r < 4; ++r) {
        int idx = t + r * 256;          // 0..1023
        int row = idx >> 3;             // 0..127
        int c4f = (idx & 7) * 4;        // 0..28 floats
        CP_ASYNC16(smbase + (unsigned)(row * 36 + c4f) * 4,
                   g + (size_t)row * HIDDEN + c4f);
    }
}

__global__ __launch_bounds__(256, 2) void tf32_gemm_kernel(
    const float* __restrict__ A0g, const float* __restrict__ A1g,
    const float* __restrict__ W0g, const float* __restrict__ W1g,
    const float* __restrict__ b0g, const float* __restrict__ b1g,
    __nv_bfloat16* __restrict__ O0g, __nv_bfloat16* __restrict__ O1g) {
    extern __shared__ __align__(16) char sm[];
    const unsigned sb = (unsigned)__cvta_generic_to_shared(sm);

    const int z = blockIdx.z;
    const float* A = (z ? A1g : A0g);
    const float* W = (z ? W1g : W0g);
    const float* bias = z ? b1g : b0g;
    __nv_bfloat16* OH = z ? O1g : O0g;

    const int t = threadIdx.x, lane = t & 31, warp = t >> 5;
    const int wm = warp >> 2, wn = warp & 3;
    const int m0 = blockIdx.y * 128, n0 = blockIdx.x * 128;
    const int g = lane >> 2, c4 = lane & 3;

    const float* A0 = A + (size_t)m0 * HIDDEN;
    const float* W0 = W + (size_t)n0 * HIDDEN;

    float acc[4][4][4] = {};

    stage_f32(sb + 0 * TF_TILE, A0, t);
    stage_f32(sb + 1 * TF_TILE, W0, t);
    CP_COMMIT();

    for (int i = 0; i < 32; ++i) {
        if (i < 31) {
            int k1 = (i + 1) * 32;
            unsigned s1 = sb + ((i + 1) & 1) * 2 * TF_TILE;
            stage_f32(s1 + 0 * TF_TILE, A0 + k1, t);
            stage_f32(s1 + 1 * TF_TILE, W0 + k1, t);
            CP_COMMIT();
            CP_WAIT(1);
        } else {
            CP_WAIT(0);
        }
        __syncthreads();

        const float* As = (const float*)(sm + (i & 1) * 2 * TF_TILE);
        const float* Ws = As + TF_TILE / 4;

#pragma unroll
        for (int s = 0; s < 4; ++s) {
            int ko = s * 8;
            float bf[4][2], af[4][4];
#pragma unroll
            for (int j = 0; j < 4; ++j) {
                int n = wn * 32 + j * 8 + g;
                bf[j][0] = Ws[n * 36 + ko + c4];
                bf[j][1] = Ws[n * 36 + ko + c4 + 4];
            }
#pragma unroll
            for (int ii = 0; ii < 4; ++ii) {
                int m = wm * 64 + ii * 16 + g;
                af[ii][0] = As[m * 36 + ko + c4];
                af[ii][1] = As[(m + 8) * 36 + ko + c4];
                af[ii][2] = As[m * 36 + ko + c4 + 4];
                af[ii][3] = As[(m + 8) * 36 + ko + c4 + 4];
            }
#pragma unroll
            for (int ii = 0; ii < 4; ++ii)
#pragma unroll
                for (int j = 0; j < 4; ++j)
                    mma_tf32(acc[ii][j], af[ii], bf[j]);
        }
        __syncthreads();
    }

    const int t2 = (lane & 3) * 2;
#pragma unroll
    for (int i = 0; i < 4; ++i) {
        int row = m0 + wm * 64 + i * 16 + g;
#pragma unroll
        for (int j = 0; j < 4; ++j) {
            int col = n0 + wn * 32 + j * 8 + t2;
            float bb0 = bias[col], bb1 = bias[col + 1];
            *(__nv_bfloat162*)&OH[(size_t)row * HIDDEN + col] =
                __float22bfloat162_rn(make_float2(acc[i][j][0] + bb0, acc[i][j][1] + bb1));
            *(__nv_bfloat162*)&OH[(size_t)(row + 8) * HIDDEN + col] =
                __float22bfloat162_rn(make_float2(acc[i][j][2] + bb0, acc[i][j][3] + bb1));
        }
    }
}

// ---------------------------------------------------------------------------
// bf16 staging (128 rows x 32 cols, stride 40) + B fragments
// ---------------------------------------------------------------------------
__device__ __forceinline__ void stage_tile(unsigned smbase, const __nv_bfloat16* g, int t) {
#pragma unroll
    for (int r = 0; r < 2; ++r) {
        int idx = t + r * 256;
        int row = idx >> 2;
        int c8  = (idx & 3) * 8;
        CP_ASYNC16(smbase + (unsigned)(row * 40 + c8) * 2, g + (size_t)row * HIDDEN + c8);
    }
}
__device__ __forceinline__ void load_bfrag(unsigned bf[4][2], const __nv_bfloat16* B,
                                           int wn, int ks, int lane) {
#pragma unroll
    for (int jj = 0; jj < 2; ++jj) {
        unsigned r[4];
        int br = wn * 32 + jj * 16 + (lane & 15);
        int bc = ks + ((lane & 16) ? 8 : 0);
        ldsm_x4(r, &B[br * 40 + bc]);
        bf[2 * jj][0] = r[0]; bf[2 * jj][1] = r[2];
        bf[2 * jj + 1][0] = r[1]; bf[2 * jj + 1][1] = r[3];
    }
}

// ---------------------------------------------------------------------------
// gemm_fast: 1-MMA bf16; grid.z selects pair; fp32 out if Of set.
// ---------------------------------------------------------------------------
__global__ __launch_bounds__(256, 2) void gemm_fast_kernel(
    const __nv_bfloat16* __restrict__ A0g, const __nv_bfloat16* __restrict__ A1g,
    const __nv_bfloat16* __restrict__ W0g, const __nv_bfloat16* __restrict__ W1g,
    const float* __restrict__ b0g, const float* __restrict__ b1g,
    __nv_bfloat16* __restrict__ O0g, __nv_bfloat16* __restrict__ O1g,
    float* __restrict__ Of) {
    __shared__ __align__(16) __nv_bfloat16 smf[2][2][128 * 40];
    const int t = threadIdx.x, lane = t & 31, warp = t >> 5;
    const int wm = warp >> 2, wn = warp & 3;
    const int m0 = blockIdx.y * 128, n0 = blockIdx.x * 128;
    const int z = blockIdx.z;

    const __nv_bfloat16* A0 = (z ? A1g : A0g) + (size_t)m0 * HIDDEN;
    const __nv_bfloat16* W0 = (z ? W1g : W0g) + (size_t)n0 * HIDDEN;
    const float* bias = z ? b1g : b0g;
    __nv_bfloat16* Obf = z ? O1g : O0g;

    float acc[4][4][4] = {};

    stage_tile((unsigned)__cvta_generic_to_shared(smf[0][0]), A0, t);
    stage_tile((unsigned)__cvta_generic_to_shared(smf[0][1]), W0, t);
    CP_COMMIT();

    for (int i = 0; i < 32; ++i) {
        if (i < 31) {
            int k1 = (i + 1) * 32;
            int s = (i + 1) & 1;
            stage_tile((unsigned)__cvta_generic_to_shared(smf[s][0]), A0 + k1, t);
            stage_tile((unsigned)__cvta_generic_to_shared(smf[s][1]), W0 + k1, t);
            CP_COMMIT();
            CP_WAIT(1);
        } else {
            CP_WAIT(0);
        }
        __syncthreads();

        const __nv_bfloat16* Ah = smf[i & 1][0];
        const __nv_bfloat16* Bh = smf[i & 1][1];

#pragma unroll
        for (int ks = 0; ks < 32; ks += 16) {
            unsigned ah[4][4], bhf[4][2];
            load_bfrag(bhf, Bh, wn, ks, lane);
#pragma unroll
            for (int ii = 0; ii < 4; ++ii) {
                int ar = wm * 64 + ii * 16 + (lane & 15);
                int ac = ks + ((lane & 16) ? 8 : 0);
                ldsm_x4(ah[ii], &Ah[ar * 40 + ac]);
            }
#pragma unroll
            for (int ii = 0; ii < 4; ++ii)
#pragma unroll
                for (int j = 0; j < 4; ++j)
                    mma_bf16(acc[ii][j], ah[ii], bhf[j]);
        }
        __syncthreads();
    }

    const int g = lane >> 2, t2 = (lane & 3) * 2;
    if (Of) {
#pragma unroll
        for (int i = 0; i < 4; ++i) {
            int row = m0 + wm * 64 + i * 16 + g;
#pragma unroll
            for (int j = 0; j < 4; ++j) {
                int col = n0 + wn * 32 + j * 8 + t2;
                float bb0 = bias[col], bb1 = bias[col + 1];
                *(float2*)&Of[(size_t)row * HIDDEN + col] =
                    make_float2(acc[i][j][0] + bb0, acc[i][j][1] + bb1);
                *(float2*)&Of[(size_t)(row + 8) * HIDDEN + col] =
                    make_float2(acc[i][j][2] + bb0, acc[i][j][3] + bb1);
            }
        }
    } else {
#pragma unroll
        for (int i = 0; i < 4; ++i) {
            int row = m0 + wm * 64 + i * 16 + g;
#pragma unroll
            for (int j = 0; j < 4; ++j) {
                int col = n0 + wn * 32 + j * 8 + t2;
                float bb0 = bias[col], bb1 = bias[col + 1];
                *(__nv_bfloat162*)&Obf[(size_t)row * HIDDEN + col] =
                    __float22bfloat162_rn(make_float2(acc[i][j][0] + bb0, acc[i][j][1] + bb1));
                *(__nv_bfloat162*)&Obf[(size_t)(row + 8) * HIDDEN + col] =
                    __float22bfloat162_rn(make_float2(acc[i][j][2] + bb0, acc[i][j][3] + bb1));
            }
        }
    }
}

// ---------------------------------------------------------------------------
// Fused attention: q-tile 64, 256 threads, 8 warps (wm4 x wn2), 2 CTAs/SM.
// S = Qh·Kh bf16 in both passes (bitwise identical).
// smem: QH 0(9216), K 9216(2x18432), V 46080(2x18432, reused as red),
//       PART 82944(512), INV 83456(256), LINV 83712(256) -> 83968
// ---------------------------------------------------------------------------
#define A_QH 0
#define A_K  9216
#define A_V  46080
#define A_PART 82944
#define A_INV  83456
#define A_LINV 83712
#define A_SMEM 83968

__device__ __forceinline__ void stage_q64(unsigned sm, const __nv_bfloat16* g, int t) {
#pragma unroll
    for (int r = 0; r < 2; ++r) {
        int idx = t + r * 256;
        int row = idx >> 3;
        int c8  = (idx & 7) * 8;
        CP_ASYNC16(sm + (unsigned)(row * 72 + c8) * 2, g + (size_t)row * HIDDEN + c8);
    }
}
__device__ __forceinline__ void stage_k128(unsigned sm, const __nv_bfloat16* g, int t) {
#pragma unroll
    for (int r = 0; r < 4; ++r) {
        int idx = t + r * 256;
        int row = idx >> 3;
        int c8  = (idx & 7) * 8;
        CP_ASYNC16(sm + (unsigned)(row * 72 + c8) * 2, g + (size_t)row * HIDDEN + c8);
    }
}

__global__ __launch_bounds__(256, 2) void attn_fused_kernel(
    const __nv_bfloat16* __restrict__ Qh,
    const __nv_bfloat16* __restrict__ Kh,
    const __nv_bfloat16* __restrict__ Vh,
    const float* __restrict__ temp,
    float* __restrict__ attn, __nv_bfloat16* __restrict__ ctx) {
    extern __shared__ __align__(16) char smraw[];
    __nv_bfloat16* q_h = (__nv_bfloat16*)(smraw + A_QH);
    float* red     = (float*)(smraw + A_V);
    float* part    = (float*)(smraw + A_PART);
    float* sm_inv  = (float*)(smraw + A_INV);
    float* sm_linv = (float*)(smraw + A_LINV);
    const unsigned sb = (unsigned)__cvta_generic_to_shared(smraw);

    const int t = threadIdx.x, lane = t & 31, wid = t >> 5;
    const int wm = wid >> 1, wn = wid & 1;
    const int bh = blockIdx.y, b = bh >> 4, h = bh & 15;
    const int q0 = blockIdx.x * 64;
    const float tsl = temp[0] * LOG2E;
    const int g = lane >> 2, t2 = (lane & 3) * 2;
    const int lr = lane & 15, hc = (lane & 16) ? 8 : 0;

    const size_t qoff = (size_t)(b * SEQ + q0) * HIDDEN + h * DH;
    const size_t koff = (size_t)(b * SEQ) * HIDDEN + h * DH;

    stage_q64(sb + A_QH, Qh + qoff, t);
    CP_COMMIT();
    stage_k128(sb + A_K, Kh + koff, t);
    stage_k128(sb + A_V, Vh + koff, t);
    CP_COMMIT();

    CP_WAIT(1);
    __syncthreads();
    unsigned aqh_f[4][4];
#pragma unroll
    for (int kd = 0; kd < 4; ++kd)
        ldsm_x4(aqh_f[kd], &q_h[(wm * 16 + lr) * 72 + kd * 16 + hc]);

    // ---------------- PASS 1: QK bf16 + ex2 + rowsum + PV (register P) ------
    float acc[8][4] = {};
    float rs0 = 0.f, rs1 = 0.f;

    for (int kt = 0; kt < 16; ++kt) {
        __syncthreads();
        if (kt < 15) {
            size_t go = (size_t)(kt + 1) * 128 * HIDDEN;
            stage_k128(sb + A_K + ((kt + 1) & 1) * 18432, Kh + koff + go, t);
            stage_k128(sb + A_V + ((kt + 1) & 1) * 18432, Vh + koff + go, t);
            CP_COMMIT();
            CP_WAIT(1);
        } else {
            CP_WAIT(0);
        }
        __syncthreads();

        const __nv_bfloat16* k_h = (const __nv_bfloat16*)(smraw + A_K + (kt & 1) * 18432);
        const __nv_bfloat16* v_h = (const __nv_bfloat16*)(smraw + A_V + (kt & 1) * 18432);

        float c[8][4] = {};
#pragma unroll
        for (int kd = 0; kd < 4; ++kd) {
#pragma unroll
            for (int jp = 0; jp < 4; ++jp) {
                unsigned bb[4];
                ldsm_x4(bb, &k_h[(wn * 64 + jp * 16 + lr) * 72 + kd * 16 + hc]);
                unsigned be[2] = {bb[0], bb[2]}, bo[2] = {bb[1], bb[3]};
                mma_bf16(c[2 * jp],     aqh_f[kd], be);
                mma_bf16(c[2 * jp + 1], aqh_f[kd], bo);
            }
        }

#pragma unroll
        for (int j = 0; j < 8; ++j) {
            c[j][0] = ex2f_fast(c[j][0] * tsl);
            c[j][1] = ex2f_fast(c[j][1] * tsl);
            c[j][2] = ex2f_fast(c[j][2] * tsl);
            c[j][3] = ex2f_fast(c[j][3] * tsl);
            rs0 += c[j][0] + c[j][1];
            rs1 += c[j][2] + c[j][3];
        }

#pragma unroll
        for (int j2 = 0; j2 < 4; ++j2) {
            unsigned ap[4];
            ap[0] = pack_bf2(c[2 * j2][0],     c[2 * j2][1]);
            ap[1] = pack_bf2(c[2 * j2][2],     c[2 * j2][3]);
            ap[2] = pack_bf2(c[2 * j2 + 1][0], c[2 * j2 + 1][1]);
            ap[3] = pack_bf2(c[2 * j2 + 1][2], c[2 * j2 + 1][3]);
#pragma unroll
            for (int djp = 0; djp < 4; ++djp) {
                unsigned bv[4];
                ldsm_x4t(bv, &v_h[(wn * 64 + j2 * 16 + lr) * 72 + djp * 16 + hc]);
                unsigned b0[2] = {bv[0], bv[1]}, b1[2] = {bv[2], bv[3]};
                mma_bf16(acc[2 * djp],     ap, b0);
                mma_bf16(acc[2 * djp + 1], ap, b1);
            }
        }
    }

    // rowsum reduce -> part[wn][64]
    rs0 += __shfl_xor_sync(0xffffffffu, rs0, 1);
    rs0 += __shfl_xor_sync(0xffffffffu, rs0, 2);
    rs1 += __shfl_xor_sync(0xffffffffu, rs1, 1);
    rs1 += __shfl_xor_sync(0xffffffffu, rs1, 2);
    if ((lane & 3) == 0) {
        part[wn * 64 + wm * 16 + g]     = rs0;
        part[wn * 64 + wm * 16 + g + 8] = rs1;
    }
    __syncthreads();

    // prefetch pass2 K0 into buffer 0
    stage_k128(sb + A_K, Kh + koff, t);
    CP_COMMIT();

    if (t < 64) {
        float s = part[t] + part[64 + t];
        sm_inv[t]  = 1.0f / s;
        sm_linv[t] = -lg2f_fast(s);
    }

    // ctx reduction across wn (deterministic 2-step) into red[64][66]
    if (wn == 0) {
#pragma unroll
        for (int dj = 0; dj < 8; ++dj) {
            int r0 = wm * 16 + g, d = dj * 8 + t2;
            red[r0 * 66 + d]           = acc[dj][0];
            red[r0 * 66 + d + 1]       = acc[dj][1];
            red[(r0 + 8) * 66 + d]     = acc[dj][2];
            red[(r0 + 8) * 66 + d + 1] = acc[dj][3];
        }
    }
    __syncthreads();
    if (wn == 1) {
#pragma unroll
        for (int dj = 0; dj < 8; ++dj) {
            int r0 = wm * 16 + g, d = dj * 8 + t2;
            red[r0 * 66 + d]           += acc[dj][0];
            red[r0 * 66 + d + 1]       += acc[dj][1];
            red[(r0 + 8) * 66 + d]     += acc[dj][2];
            red[(r0 + 8) * 66 + d + 1] += acc[dj][3];
        }
    }
    __syncthreads();

    // ctx = red * inv (bf16)
    {
        int row = t >> 2, d0 = (t & 3) * 16;
        float iv = sm_inv[row];
        size_t o = (size_t)(b * SEQ + q0 + row) * HIDDEN + h * DH + d0;
#pragma unroll
        for (int u = 0; u < 8; ++u) {
            float x = red[row * 66 + d0 + 2 * u]     * iv;
            float y = red[row * 66 + d0 + 2 * u + 1] * iv;
            *(__nv_bfloat162*)&ctx[o + 2 * u] =
                __float22bfloat162_rn(make_float2(x, y));
        }
    }

    // ---------------- PASS 2: identical S, p = ex2(c*tsl + linv) ------------
    for (int kt = 0; kt < 16; ++kt) {
        __syncthreads();
        if (kt < 15) {
            size_t go = (size_t)(kt + 1) * 128 * HIDDEN;
            stage_k128(sb + A_K + ((kt + 1) & 1) * 18432, Kh + koff + go, t);
            CP_COMMIT();
            CP_WAIT(1);
        } else {
            CP_WAIT(0);
        }
        __syncthreads();

        const __nv_bfloat16* k_h = (const __nv_bfloat16*)(smraw + A_K + (kt & 1) * 18432);

        float c[8][4] = {};
#pragma unroll
        for (int kd = 0; kd < 4; ++kd) {
#pragma unroll
            for (int jp = 0; jp < 4; ++jp) {
                unsigned bb[4];
                ldsm_x4(bb, &k_h[(wn * 64 + jp * 16 + lr) * 72 + kd * 16 + hc]);
                unsigned be[2] = {bb[0], bb[2]}, bo[2] = {bb[1], bb[3]};
                mma_bf16(c[2 * jp],     aqh_f[kd], be);
                mma_bf16(c[2 * jp + 1], aqh_f[kd], bo);
            }
        }

        int rl = wm * 16 + g;
        float li0 = sm_linv[rl], li1 = sm_linv[rl + 8];
        size_t r0 = ((size_t)bh * SEQ + q0 + rl) * SEQ + (size_t)kt * 128 + wn * 64;
        size_t r1 = r0 + (size_t)8 * SEQ;
#pragma unroll
        for (int j = 0; j < 8; ++j) {
            float p0 = ex2f_fast(fmaf(c[j][0], tsl, li0));
            float p1 = ex2f_fast(fmaf(c[j][1], tsl, li0));
            float p2 = ex2f_fast(fmaf(c[j][2], tsl, li1));
            float p3 = ex2f_fast(fmaf(c[j][3], tsl, li1));
            int col = j * 8 + t2;
            *(float2*)&attn[r0 + col] = make_float2(p0, p1);
            *(float2*)&attn[r1 + col] = make_float2(p2, p3);
        }
    }
}

// ---------------------------------------------------------------------------
// LayerNorm(proj + query) -> out
// ---------------------------------------------------------------------------
__global__ void ln_kernel(const float* __restrict__ proj,
                          const float* __restrict__ query,
                          const float* __restrict__ gamma,
                          const float* __restrict__ beta,
                          float* __restrict__ out) {
    __shared__ float red[8];
    const size_t row = blockIdx.x;
    const int t = threadIdx.x;

    float x[4];
    float s = 0.f;
#pragma unroll
    for (int i = 0; i < 4; ++i) {
        int c = t + i * 256;
        x[i] = proj[row * HIDDEN + c] + query[row * HIDDEN + c];
        s += x[i];
    }
#pragma unroll
    for (int o = 16; o; o >>= 1) s += __shfl_xor_sync(0xffffffffu, s, o);
    if ((t & 31) == 0) red[t >> 5] = s;
    __syncthreads();
    s = red[0];
#pragma unroll
    for (int i = 1; i < 8; ++i) s += red[i];
    const float mu = s * (1.f / HIDDEN);

    float vs = 0.f;
#pragma unroll
    for (int i = 0; i < 4; ++i) { float d = x[i] - mu; vs += d * d; }
#pragma unroll
    for (int o = 16; o; o >>= 1) vs += __shfl_xor_sync(0xffffffffu, vs, o);
    __syncthreads();
    if ((t & 31) == 0) red[t >> 5] = vs;
    __syncthreads();
    vs = red[0];
#pragma unroll
    for (int i = 1; i < 8; ++i) vs += red[i];
    const float inv = rsqrtf(vs * (1.f / HIDDEN) + LN_EPS);

#pragma unroll
    for (int i = 0; i < 4; ++i) {
        int c = t + i * 256;
        out[row * HIDDEN + c] = (x[i] - mu) * inv * gamma[c] + beta[c];
    }
}

// ---------------------------------------------------------------------------
// Launch
// ---------------------------------------------------------------------------
extern "C" void kernel_launch(void* const* d_in, const int* in_sizes, int n_in,
                              void* d_out, int out_size) {
    const float* query = (const float*)d_in[0];
    const float* key   = (const float*)d_in[1];
    const float* value = (const float*)d_in[2];
    const float* Wq    = (const float*)d_in[3];
    const float* bq    = (const float*)d_in[4];
    const float* Wk    = (const float*)d_in[5];
    const float* bk    = (const float*)d_in[6];
    const float* Wv    = (const float*)d_in[7];
    const float* bv    = (const float*)d_in[8];
    const float* Wo    = (const float*)d_in[9];
    const float* bo    = (const float*)d_in[10];
    const float* gamma = (const float*)d_in[11];
    const float* beta  = (const float*)d_in[12];
    const float* temp  = (const float*)d_in[13];

    float* out  = (float*)d_out;
    float* attn = out + (size_t)MROWS * HIDDEN;

    __nv_bfloat16 *Wvh, *Woh, *Xvh;
    __nv_bfloat16 *Qhp, *Khp, *Vhp, *ctxp;
    float *projp;
    cudaGetSymbolAddress((void**)&Wvh, g_Wvh);
    cudaGetSymbolAddress((void**)&Woh, g_Woh);
    cudaGetSymbolAddress((void**)&Xvh, g_Xvh);
    cudaGetSymbolAddress((void**)&Qhp, g_Qh);
    cudaGetSymbolAddress((void**)&Khp, g_Kh);
    cudaGetSymbolAddress((void**)&Vhp, g_Vh);
    cudaGetSymbolAddress((void**)&ctxp, g_ctx);
    cudaGetSymbolAddress((void**)&projp, g_proj);

    cudaFuncSetAttribute(tf32_gemm_kernel,
                         cudaFuncAttributeMaxDynamicSharedMemorySize, TF_SMEM);
    cudaFuncSetAttribute(attn_fused_kernel,
                         cudaFuncAttributeMaxDynamicSharedMemorySize, A_SMEM);

    // Q + K projections (tf32, straight from fp32 inputs)
    dim3 qk_grid(HIDDEN / 128, MROWS / 128, 2);
    tf32_gemm_kernel<<<qk_grid, 256, TF_SMEM>>>(query, key, Wq, Wk, bq, bk,
                                                Qhp, Khp);

    // presplit (V path only)
    dim3 ps_grid(X4 / 256, 3);
    presplit3<<<ps_grid, 256>>>(Wv, Wo, value, Wvh, Woh, Xvh);

    // V projection
    dim3 pgrid(HIDDEN / 128, MROWS / 128);
    gemm_fast_kernel<<<pgrid, 256>>>(Xvh, Xvh, Wvh, Wvh, bv, bv,
                                     Vhp, Vhp, nullptr);

    // fused attention (q-tile 64, 2 CTAs/SM)
    dim3 at_grid(SEQ / 64, NBATCH * HEADS);   // (32, 32)
    attn_fused_kernel<<<at_grid, 256, A_SMEM>>>(Qhp, Khp, Vhp, temp, attn, ctxp);

    // output projection + LN
    gemm_fast_kernel<<<pgrid, 256>>>(ctxp, ctxp, Woh, Woh, bo, bo,
                                     nullptr, nullptr, projp);
    ln_kernel<<<MROWS, 256>>>(projp, query, gamma, beta, out);
}